// round 14
// baseline (speedup 1.0000x reference)
#include <cuda_runtime.h>
#include <cuda_bf16.h>
#include <cuda_fp16.h>
#include <cstdint>
#include <math.h>

#define DI __device__ __forceinline__
typedef unsigned short u16;

constexpr int TOK = 32768;           // 8 * 64 * 64
constexpr float EPS = 1e-5f;
constexpr int CH = 64;               // tokens per chunk
constexpr int CHUNKS = TOK / CH;     // 512

// ---------------------------------------------------------------------------
// Device scratch
// ---------------------------------------------------------------------------
__device__ __align__(16) u16   g_a2[TOK * 128];        // x1, fp16 single plane
__device__ __align__(16) u16   g_val[TOK * 128];       // value, fp16
__device__ __align__(16) float g_om[TOK * 64];         // offset/mask, fp32 (27 used, rest 0)
__device__ __align__(16) u16   g_dcn[TOK * 128];       // fp16 single
__device__ __align__(16) float g_op[TOK * 128];        // fp32 token-major

__device__ __align__(16) u16 g_w1h[128 * 128], g_w1l[128 * 128];   // fp16
__device__ __align__(16) u16 g_w2h[192 * 128], g_w2l[192 * 128];   // fp16
__device__ __align__(16) u16 g_w4h[128 * 128], g_w4l[128 * 128];   // fp16
__device__ __align__(16) u16 g_w5h[128 * 128], g_w5l[128 * 128];   // fp16
__device__ float g_bias0[128], g_bias1[128], g_bcat[192], g_zero[192];

// ---------------------------------------------------------------------------
// Helpers
// ---------------------------------------------------------------------------
DI uint32_t smem_u32(const void* p) {
    uint32_t a;
    asm("{ .reg .u64 t; cvta.to.shared.u64 t, %1; cvt.u32.u64 %0, t; }" : "=r"(a) : "l"(p));
    return a;
}

DI void cpa16(uint32_t dst, const void* src) {
    asm volatile("{ .reg .u64 g; cvta.to.global.u64 g, %1; "
                 "cp.async.cg.shared.global [%0], [g], 16; }"
                 :: "r"(dst), "l"(src));
}
DI void cpa_commit() { asm volatile("cp.async.commit_group;" ::: "memory"); }
DI void cpa_wait0() { asm volatile("cp.async.wait_group 0;" ::: "memory"); }
DI void cpa_wait1() { asm volatile("cp.async.wait_group 1;" ::: "memory"); }

DI void ldsm4(uint32_t (&r)[4], uint32_t addr) {
    asm volatile("ldmatrix.sync.aligned.m8n8.x4.shared.b16 {%0,%1,%2,%3}, [%4];"
                 : "=r"(r[0]), "=r"(r[1]), "=r"(r[2]), "=r"(r[3]) : "r"(addr));
}

DI void mma_f16(float (&d)[4], const uint32_t (&a)[4], uint32_t b0, uint32_t b1) {
    asm volatile("mma.sync.aligned.m16n8k16.row.col.f32.f16.f16.f32 "
                 "{%0,%1,%2,%3}, {%4,%5,%6,%7}, {%8,%9}, {%0,%1,%2,%3};"
                 : "+f"(d[0]), "+f"(d[1]), "+f"(d[2]), "+f"(d[3])
                 : "r"(a[0]), "r"(a[1]), "r"(a[2]), "r"(a[3]), "r"(b0), "r"(b1));
}

// XOR-swizzled 16-bit tile: row stride 256 B (128 elems), 16B chunk c -> c ^ (row&7)
DI uint32_t tile_off(int r, int chunk) { return (uint32_t)(r * 256 + ((chunk ^ (r & 7)) << 4)); }

DI uint32_t cvtf16x2(float f0, float f1) {             // {hi=f1, lo=f0}
    uint32_t r;
    asm("cvt.rn.f16x2.f32 %0, %1, %2;" : "=r"(r) : "f"(f1), "f"(f0));
    return r;
}

// ---------------------------------------------------------------------------
// Merged prep: fold BN, transpose to [n][k], split all weights to fp16 hi/lo
// (exact two-term split), plus biases.
// ---------------------------------------------------------------------------
__global__ void prep_all(const float* __restrict__ w_pw0, const float* __restrict__ w_pw1,
                         const float* __restrict__ w_vp,  const float* __restrict__ w_om,
                         const float* __restrict__ w_op,
                         const float* __restrict__ bn1_g, const float* __restrict__ bn1_b,
                         const float* __restrict__ bn1_m, const float* __restrict__ bn1_v,
                         const float* __restrict__ bn2_g, const float* __restrict__ bn2_b,
                         const float* __restrict__ bn2_m, const float* __restrict__ bn2_v,
                         const float* __restrict__ b_vp,  const float* __restrict__ b_om)
{
    int idx = blockIdx.x * blockDim.x + threadIdx.x;
    if (idx < 73728) {
        float w; u16 *H, *L; int off;
        if (idx < 16384) {                       // pw0 * BN1
            int k = idx & 127;
            w = w_pw0[idx] * bn1_g[k] * rsqrtf(bn1_v[k] + EPS);
            H = g_w1h; L = g_w1l; off = idx;
        } else if (idx < 32768) {                // pw1 * BN2
            int j = idx - 16384; int k = j & 127;
            w = w_pw1[j] * bn2_g[k] * rsqrtf(bn2_v[k] + EPS);
            H = g_w5h; L = g_w5l; off = j;
        } else if (idx < 49152) {                // w_op^T
            int j = idx - 32768; int n = j >> 7, k = j & 127;
            w = w_op[k * 128 + n];
            H = g_w4h; L = g_w4l; off = j;
        } else {                                 // [w_vp|w_om]^T padded to 192
            int j = idx - 49152; int n = j >> 7, k = j & 127;
            w = (n < 128) ? w_vp[k * 128 + n] : ((n < 155) ? w_om[k * 32 + (n - 128)] : 0.f);
            H = g_w2h; L = g_w2l; off = j;
        }
        __half h = __float2half_rn(w);
        H[off] = __half_as_ushort(h);
        L[off] = __half_as_ushort(__float2half_rn(w - __half2float(h)));
    } else if (idx < 73856) {
        int o = idx - 73728;
        float s = 0.f;
        for (int c = 0; c < 128; ++c) {
            float sc = bn1_g[c] * rsqrtf(bn1_v[c] + EPS);
            s += w_pw0[o * 128 + c] * (bn1_b[c] - bn1_m[c] * sc);
        }
        g_bias0[o] = s;
    } else if (idx < 73984) {
        int o = idx - 73856;
        float s = 0.f;
        for (int c = 0; c < 128; ++c) {
            float sc = bn2_g[c] * rsqrtf(bn2_v[c] + EPS);
            s += w_pw1[o * 128 + c] * (bn2_b[c] - bn2_m[c] * sc);
        }
        g_bias1[o] = s;
    } else if (idx < 74176) {
        int j = idx - 73984;
        g_bcat[j] = (j < 128) ? b_vp[j] : ((j < 155) ? b_om[j - 128] : 0.f);
        g_zero[j] = 0.f;
    }
}

// ---------------------------------------------------------------------------
// Persistent chunk-loop HMMA GEMM (fp16 2-pass: A single fp16, B exact
// fp16 hi/lo split; fp32 accum).
//  AKM=true : A read fp32 k-major (NCHW raw view); frags via LDS + cvt.
// MODE 0: fp32 row-major reg stores (token-major, ldo)
// MODE 1: raw-reshape scatter (B,C,HW)->(B,HW,C), fp16 single plane out
// MODE 2: fp32 NCHW final output
// MODE 3: split store (N=192): cols 0-127 -> fp16 outH (ld 128);
//         cols 128-191 -> fp32 outF (ld 64). Direct register stores.
// 8 warps = 2m(32) x 4n(N/4); CH=64 chunks, cp.async double buffer.
// ---------------------------------------------------------------------------
template<int N, int MODE, bool AKM>
__global__ void __launch_bounds__(256, 1)
gemm_mma(const float* __restrict__ Af, const u16* __restrict__ A0,
         const u16* __restrict__ B0, const u16* __restrict__ B1,
         const float* __restrict__ biasj,
         float* __restrict__ outF, int ldo, u16* __restrict__ outH)
{
    constexpr int NW = N / 4;
    constexpr int NT = NW / 8;
    constexpr int NP = NW / 16;
    constexpr int BOFF = 2 * N * 256;
    constexpr int ABUF = AKM ? (128 * 272) : (CH * 256);
    constexpr int ldp = N + 1;

    extern __shared__ char sm[];
    const uint32_t uSM = smem_u32(sm);
    const uint32_t uBh = uSM, uBl = uSM + N * 256;
    float* stage = (float*)(sm + BOFF + 2 * ABUF);

    const int t = threadIdx.x, w = t >> 5, l = t & 31;
    const int wm = w & 1, wn = w >> 1;
    const int nb0 = wn * NW;

    const int cbase = (l & 3) * 2;
    float bj0[NT], bj1[NT];
#pragma unroll
    for (int nt = 0; nt < NT; nt++) {
        int col = nb0 + nt * 8 + cbase;
        bj0[nt] = biasj[col];
        bj1[nt] = biasj[col + 1];
    }

    // B load (once)
    {
        const uint4* sh_ = (const uint4*)B0;
        const uint4* sl_ = (const uint4*)B1;
        for (int i = t; i < N * 16; i += 256) {
            int r = i >> 4, c = i & 15;
            uint32_t o = tile_off(r, c);
            cpa16(uBh + o, sh_ + i);
            cpa16(uBl + o, sl_ + i);
        }
    }
    cpa_commit();

    auto loadA = [&](uint32_t dst, int cid_) {
        size_t m0 = (size_t)cid_ * CH;
        if constexpr (AKM) {
            const float* base = Af + (m0 >> 12) * 524288 + (m0 & 4095);
            for (int i = t; i < 2048; i += 256) {
                int k = i >> 4, u = i & 15;
                cpa16(dst + (uint32_t)(k * 272 + u * 16), base + (size_t)k * 4096 + u * 4);
            }
        } else {
            const uint4* s0 = (const uint4*)(A0 + m0 * 128);
            for (int i = t; i < 1024; i += 256) {
                int r = i >> 4, c = i & 15;
                cpa16(dst + tile_off(r, c), s0 + i);
            }
        }
    };

    int cid = blockIdx.x;
    loadA(uSM + BOFF, cid);
    cpa_commit();

    const int arow_lo = wm * 32 + (l & 15);
    const int akhalf = l >> 4;
    const int brow_off = (l & 7) + ((l & 16) >> 1);
    const int bkhalf = (l >> 3) & 1;
    const int mfrag = wm * 32 + (l >> 2);
    const int kfrag = (l & 3) * 2;

    int p = 0;
    while (cid < CHUNKS) {
        const int nxt = cid + (int)gridDim.x;
        const bool hasnext = nxt < CHUNKS;
        if (hasnext) {
            loadA(uSM + BOFF + (p ^ 1) * ABUF, nxt);
            cpa_commit();
            cpa_wait1();
        } else {
            cpa_wait0();
        }
        __syncthreads();

        const uint32_t uA = uSM + BOFF + p * ABUF;
        const float* tileA = (const float*)(sm + BOFF + p * ABUF);

        float d[2][NT][4];
#pragma unroll
        for (int mt = 0; mt < 2; mt++)
#pragma unroll
            for (int nt = 0; nt < NT; nt++)
#pragma unroll
                for (int i = 0; i < 4; i++) d[mt][nt][i] = 0.f;

#pragma unroll
        for (int ks = 0; ks < 8; ks++) {
            uint32_t bh[NP][4], bl[NP][4];
#pragma unroll
            for (int np = 0; np < NP; np++) {
                uint32_t off = tile_off(nb0 + np * 16 + brow_off, 2 * ks + bkhalf);
                ldsm4(bh[np], uBh + off);
                ldsm4(bl[np], uBl + off);
            }
            uint32_t a[2][4];
            if constexpr (AKM) {
#pragma unroll
                for (int mt = 0; mt < 2; mt++) {
                    int mlo = mfrag + mt * 16;
                    int k0 = ks * 16 + kfrag;
                    a[mt][0] = cvtf16x2(tileA[(k0    ) * 68 + mlo],
                                        tileA[(k0 + 1) * 68 + mlo]);
                    a[mt][1] = cvtf16x2(tileA[(k0    ) * 68 + mlo + 8],
                                        tileA[(k0 + 1) * 68 + mlo + 8]);
                    a[mt][2] = cvtf16x2(tileA[(k0 + 8) * 68 + mlo],
                                        tileA[(k0 + 9) * 68 + mlo]);
                    a[mt][3] = cvtf16x2(tileA[(k0 + 8) * 68 + mlo + 8],
                                        tileA[(k0 + 9) * 68 + mlo + 8]);
                }
            } else {
#pragma unroll
                for (int mt = 0; mt < 2; mt++)
                    ldsm4(a[mt], uA + tile_off(arow_lo + mt * 16, 2 * ks + akhalf));
            }
            // pass 1: A*Bh
#pragma unroll
            for (int np = 0; np < NP; np++)
#pragma unroll
                for (int mt = 0; mt < 2; mt++) {
                    mma_f16(d[mt][2 * np],     a[mt], bh[np][0], bh[np][1]);
                    mma_f16(d[mt][2 * np + 1], a[mt], bh[np][2], bh[np][3]);
                }
            // pass 2: A*Bl
#pragma unroll
            for (int np = 0; np < NP; np++)
#pragma unroll
                for (int mt = 0; mt < 2; mt++) {
                    mma_f16(d[mt][2 * np],     a[mt], bl[np][0], bl[np][1]);
                    mma_f16(d[mt][2 * np + 1], a[mt], bl[np][2], bl[np][3]);
                }
        }

        const size_t m0 = (size_t)cid * CH;
        const int rloc = wm * 32 + (l >> 2);

        if (MODE == 0) {
#pragma unroll
            for (int mt = 0; mt < 2; mt++)
#pragma unroll
                for (int nt = 0; nt < NT; nt++) {
                    int row = rloc + mt * 16;
                    int col = nb0 + nt * 8 + cbase;
                    float2 v0 = make_float2(d[mt][nt][0] + bj0[nt], d[mt][nt][1] + bj1[nt]);
                    float2 v1 = make_float2(d[mt][nt][2] + bj0[nt], d[mt][nt][3] + bj1[nt]);
                    *(float2*)(outF + (m0 + row) * (size_t)ldo + col) = v0;
                    *(float2*)(outF + (m0 + row + 8) * (size_t)ldo + col) = v1;
                }
        } else if (MODE == 3) {
            // split: cols<128 -> fp16 outH (ld 128); cols>=128 -> fp32 outF (ld 64)
#pragma unroll
            for (int mt = 0; mt < 2; mt++)
#pragma unroll
                for (int nt = 0; nt < NT; nt++) {
                    int row = rloc + mt * 16;
                    int col = nb0 + nt * 8 + cbase;
                    float v0 = d[mt][nt][0] + bj0[nt], v1 = d[mt][nt][1] + bj1[nt];
                    float v2 = d[mt][nt][2] + bj0[nt], v3 = d[mt][nt][3] + bj1[nt];
                    if (col < 128) {
                        *(uint32_t*)(outH + (m0 + row) * 128 + col)     = cvtf16x2(v0, v1);
                        *(uint32_t*)(outH + (m0 + row + 8) * 128 + col) = cvtf16x2(v2, v3);
                    } else {
                        *(float2*)(outF + (m0 + row) * 64 + (col - 128))     = make_float2(v0, v1);
                        *(float2*)(outF + (m0 + row + 8) * 64 + (col - 128)) = make_float2(v2, v3);
                    }
                }
        } else {
#pragma unroll
            for (int mt = 0; mt < 2; mt++)
#pragma unroll
                for (int nt = 0; nt < NT; nt++) {
                    int row = rloc + mt * 16;
                    int col = nb0 + nt * 8 + cbase;
                    stage[row * ldp + col]           = d[mt][nt][0] + bj0[nt];
                    stage[row * ldp + col + 1]       = d[mt][nt][1] + bj1[nt];
                    stage[(row + 8) * ldp + col]     = d[mt][nt][2] + bj0[nt];
                    stage[(row + 8) * ldp + col + 1] = d[mt][nt][3] + bj1[nt];
                }
            __syncthreads();
            if (MODE == 1) {
                const int b  = (int)(m0 >> 12);
                const int sh = (int)((m0 & 4095) >> 7);
                const int cb = (int)(m0 & 64);
                for (int i = t; i < N * 16; i += 256) {
                    int n = i >> 4, q = i & 15, j0 = q * 4;
                    float v0 = stage[(j0 + 0) * ldp + n], v1 = stage[(j0 + 1) * ldp + n];
                    float v2 = stage[(j0 + 2) * ldp + n], v3 = stage[(j0 + 3) * ldp + n];
                    size_t row = (size_t)b * 4096 + (size_t)n * 32 + sh;
                    uint2 o;
                    o.x = cvtf16x2(v0, v1);
                    o.y = cvtf16x2(v2, v3);
                    ((uint2*)(outH + row * 128 + cb))[q] = o;
                }
            } else {
                const int b  = (int)(m0 >> 12);
                const int s0 = (int)(m0 & 4095);
                for (int i = t; i < N * 16; i += 256) {
                    int n = i >> 4, q = i & 15, j0 = q * 4;
                    float4 v = make_float4(stage[(j0 + 0) * ldp + n], stage[(j0 + 1) * ldp + n],
                                           stage[(j0 + 2) * ldp + n], stage[(j0 + 3) * ldp + n]);
                    *(float4*)(outF + (size_t)b * 524288 + (size_t)n * 4096 + s0 + j0) = v;
                }
            }
        }
        __syncthreads();
        p ^= 1;
        cid = nxt;
    }
}

// ---------------------------------------------------------------------------
// DCNv4 core v5 — two positions per warp, uint4 gathers, half2 interp.
// Half-warp h (lanes 16h..16h+15) owns position pos = base + h; each lane
// covers 8 fp16 channels. Setup lanes hl=0..8 of each half compute the
// bilinear weights/offsets for kernel point k=hl; main loop shuffles them
// with src = (lane&16)|k so one shfl serves both halves.
// ---------------------------------------------------------------------------
__global__ void __launch_bounds__(256, 8)
dcn_kernel(const u16* __restrict__ val, const float* __restrict__ om,
           u16* __restrict__ oh)
{
    const int warp = threadIdx.x >> 5;
    const int lane = threadIdx.x & 31;
    const int half = lane >> 4;
    const int hl   = lane & 15;
    const int pos  = blockIdx.x * 16 + warp * 2 + half;   // 16-aligned blocks: no batch straddle
    const int b = pos >> 12;
    const int s = pos & 4095;
    const int h = s >> 6;
    const int w = s & 63;

    // --- setup: lanes hl 0..8 meaningful; 9..15 compute harmless clamped data ---
    uint32_t wb00, wb10, wb01, wb11;
    int      o00, o10, o01, o11;
    {
        const int k = hl;                        // om cols 27..63 are exact zeros
        const float* omp = om + (size_t)pos * 64 + 3 * min(k, 15);
        float dx = omp[0], dy = omp[1], m = omp[2];
        int ky = k / 3, kx = k - ky * 3;
        float px = (float)(w + kx - 1) + dx;
        float py = (float)(h + ky - 1) + dy;
        float xf = floorf(px), yf = floorf(py);
        float fx = px - xf, fy = py - yf;
        int x0 = (int)xf, y0 = (int)yf;
        int x1 = x0 + 1,  y1 = y0 + 1;
        float vx0 = (x0 >= 0 && x0 < 64) ? m : 0.f;
        float vx1 = (x1 >= 0 && x1 < 64) ? m : 0.f;
        float gy0 = (y0 >= 0 && y0 < 64) ? 1.f : 0.f;
        float gy1 = (y1 >= 0 && y1 < 64) ? 1.f : 0.f;
        float gx0 = 1.f - fx, gy0f = 1.f - fy;
        float w00 = gx0 * gy0f * vx0 * gy0;
        float w10 = fx  * gy0f * vx1 * gy0;
        float w01 = gx0 * fy   * vx0 * gy1;
        float w11 = fx  * fy   * vx1 * gy1;
        wb00 = cvtf16x2(w00, w00);
        wb10 = cvtf16x2(w10, w10);
        wb01 = cvtf16x2(w01, w01);
        wb11 = cvtf16x2(w11, w11);
        int xc0 = min(max(x0, 0), 63), xc1 = min(max(x1, 0), 63);
        int yc0 = min(max(y0, 0), 63), yc1 = min(max(y1, 0), 63);
        o00 = (yc0 * 64 + xc0) * 128;
        o10 = (yc0 * 64 + xc1) * 128;
        o01 = (yc1 * 64 + xc0) * 128;
        o11 = (yc1 * 64 + xc1) * 128;
    }

    const u16* vbc = val + (((size_t)b << 12) * 128) + (hl << 3);
    float acc[8];
#pragma unroll
    for (int i = 0; i < 8; i++) acc[i] = 0.f;
    const unsigned FULL = 0xffffffffu;
    const int sbase = lane & 16;

#pragma unroll
    for (int k = 0; k < 9; ++k) {
        const int src = sbase | k;
        int a0 = __shfl_sync(FULL, o00, src);
        int a1 = __shfl_sync(FULL, o10, src);
        int a2 = __shfl_sync(FULL, o01, src);
        int a3 = __shfl_sync(FULL, o11, src);
        uint32_t u0 = __shfl_sync(FULL, wb00, src);
        uint32_t u1 = __shfl_sync(FULL, wb10, src);
        uint32_t u2 = __shfl_sync(FULL, wb01, src);
        uint32_t u3 = __shfl_sync(FULL, wb11, src);
        uint4 r0 = *(const uint4*)(vbc + a0);
        uint4 r1 = *(const uint4*)(vbc + a1);
        uint4 r2 = *(const uint4*)(vbc + a2);
        uint4 r3 = *(const uint4*)(vbc + a3);
        __half2 h0 = *(__half2*)&u0, h1 = *(__half2*)&u1;
        __half2 h2 = *(__half2*)&u2, h3 = *(__half2*)&u3;
        __half2 pa = __hmul2(h0, *(__half2*)&r0.x);
        __half2 pb = __hmul2(h0, *(__half2*)&r0.y);
        __half2 pc = __hmul2(h0, *(__half2*)&r0.z);
        __half2 pd = __hmul2(h0, *(__half2*)&r0.w);
        pa = __hfma2(h1, *(__half2*)&r1.x, pa);
        pb = __hfma2(h1, *(__half2*)&r1.y, pb);
        pc = __hfma2(h1, *(__half2*)&r1.z, pc);
        pd = __hfma2(h1, *(__half2*)&r1.w, pd);
        pa = __hfma2(h2, *(__half2*)&r2.x, pa);
        pb = __hfma2(h2, *(__half2*)&r2.y, pb);
        pc = __hfma2(h2, *(__half2*)&r2.z, pc);
        pd = __hfma2(h2, *(__half2*)&r2.w, pd);
        pa = __hfma2(h3, *(__half2*)&r3.x, pa);
        pb = __hfma2(h3, *(__half2*)&r3.y, pb);
        pc = __hfma2(h3, *(__half2*)&r3.z, pc);
        pd = __hfma2(h3, *(__half2*)&r3.w, pd);
        float2 fa = __half22float2(pa);
        float2 fb = __half22float2(pb);
        float2 fc = __half22float2(pc);
        float2 fd = __half22float2(pd);
        acc[0] += fa.x; acc[1] += fa.y; acc[2] += fb.x; acc[3] += fb.y;
        acc[4] += fc.x; acc[5] += fc.y; acc[6] += fd.x; acc[7] += fd.y;
    }
    uint4 o;
    o.x = cvtf16x2(acc[0], acc[1]);
    o.y = cvtf16x2(acc[2], acc[3]);
    o.z = cvtf16x2(acc[4], acc[5]);
    o.w = cvtf16x2(acc[6], acc[7]);
    *(uint4*)(oh + (size_t)pos * 128 + (hl << 3)) = o;
}

// ---------------------------------------------------------------------------
// Launcher
// ---------------------------------------------------------------------------
extern "C" void kernel_launch(void* const* d_in, const int* in_sizes, int n_in,
                              void* d_out, int out_size)
{
    (void)in_sizes; (void)n_in; (void)out_size;
    const float* x     = (const float*)d_in[0];
    const float* bn1_g = (const float*)d_in[1];
    const float* bn1_b = (const float*)d_in[2];
    const float* bn1_m = (const float*)d_in[3];
    const float* bn1_v = (const float*)d_in[4];
    const float* w_pw0 = (const float*)d_in[5];
    const float* w_vp  = (const float*)d_in[6];
    const float* b_vp  = (const float*)d_in[7];
    const float* w_om  = (const float*)d_in[8];
    const float* b_om  = (const float*)d_in[9];
    const float* w_op  = (const float*)d_in[10];
    const float* bn2_g = (const float*)d_in[11];
    const float* bn2_b = (const float*)d_in[12];
    const float* bn2_m = (const float*)d_in[13];
    const float* bn2_v = (const float*)d_in[14];
    const float* w_pw1 = (const float*)d_in[15];
    float* out = (float*)d_out;

    u16 *a2, *val, *dcn;
    u16 *w1h, *w1l, *w2h, *w2l, *w4h, *w4l, *w5h, *w5l;
    float *omb, *op, *bias0, *bias1, *bcat, *zero;
    cudaGetSymbolAddress((void**)&a2, g_a2);
    cudaGetSymbolAddress((void**)&val, g_val);    cudaGetSymbolAddress((void**)&omb, g_om);
    cudaGetSymbolAddress((void**)&dcn, g_dcn);    cudaGetSymbolAddress((void**)&op, g_op);
    cudaGetSymbolAddress((void**)&w1h, g_w1h);    cudaGetSymbolAddress((void**)&w1l, g_w1l);
    cudaGetSymbolAddress((void**)&w2h, g_w2h);    cudaGetSymbolAddress((void**)&w2l, g_w2l);
    cudaGetSymbolAddress((void**)&w4h, g_w4h);    cudaGetSymbolAddress((void**)&w4l, g_w4l);
    cudaGetSymbolAddress((void**)&w5h, g_w5h);    cudaGetSymbolAddress((void**)&w5l, g_w5l);
    cudaGetSymbolAddress((void**)&bias0, g_bias0); cudaGetSymbolAddress((void**)&bias1, g_bias1);
    cudaGetSymbolAddress((void**)&bcat, g_bcat);  cudaGetSymbolAddress((void**)&zero, g_zero);

    const int SM_G1 = 65536 + 2 * 128 * 272 + 64 * 129 * 4;
    const int SM_G2 = 98304 + 2 * 64 * 256;
    const int SM_G4 = 65536 + 2 * 64 * 256;
    const int SM_G5 = 65536 + 2 * 128 * 272 + 64 * 129 * 4;
    cudaFuncSetAttribute((const void*)gemm_mma<128, 1, true>,
                         cudaFuncAttributeMaxDynamicSharedMemorySize, SM_G1);
    cudaFuncSetAttribute((const void*)gemm_mma<192, 3, false>,
                         cudaFuncAttributeMaxDynamicSharedMemorySize, SM_G2);
    cudaFuncSetAttribute((const void*)gemm_mma<128, 0, false>,
                         cudaFuncAttributeMaxDynamicSharedMemorySize, SM_G4);
    cudaFuncSetAttribute((const void*)gemm_mma<128, 2, true>,
                         cudaFuncAttributeMaxDynamicSharedMemorySize, SM_G5);

    const int GRID = 148;

    prep_all<<<290, 256>>>(w_pw0, w_pw1, w_vp, w_om, w_op,
                           bn1_g, bn1_b, bn1_m, bn1_v,
                           bn2_g, bn2_b, bn2_m, bn2_v, b_vp, b_om);

    // 1) x1 = x(NCHW fp32 k-major) @ w1^T + bias0 -> fp16 single scatter
    gemm_mma<128, 1, true><<<GRID, 256, SM_G1>>>(
        x, nullptr, w1h, w1l, bias0, nullptr, 0, a2);

    // 2) vpom split: value -> fp16 g_val, offset/mask -> fp32 g_om (ld 64)
    gemm_mma<192, 3, false><<<GRID, 256, SM_G2>>>(
        nullptr, a2, w2h, w2l, bcat, omb, 0, val);

    // 3) DCNv4 core (2 positions/warp, uint4 fp16 gathers) -> fp16 plane
    dcn_kernel<<<2048, 256>>>(val, omb, dcn);

    // 4) op = dcn @ w_op -> fp32 token-major (the NCHW raw view for step 5)
    gemm_mma<128, 0, false><<<GRID, 256, SM_G4>>>(
        nullptr, dcn, w4h, w4l, zero, op, 128, nullptr);

    // 5) out = (BN2-folded pw1) @ op(NCHW view, fp32 k-major read) -> fp32 NCHW
    gemm_mma<128, 2, true><<<GRID, 256, SM_G5>>>(
        op, nullptr, w5h, w5l, bias1, out, 0, nullptr);
}

// round 15
// speedup vs baseline: 1.1758x; 1.1758x over previous
#include <cuda_runtime.h>
#include <cuda_bf16.h>
#include <cuda_fp16.h>
#include <cstdint>
#include <math.h>

#define DI __device__ __forceinline__
typedef unsigned short u16;

constexpr int TOK = 32768;           // 8 * 64 * 64
constexpr float EPS = 1e-5f;
constexpr int CH = 64;               // tokens per chunk
constexpr int CHUNKS = TOK / CH;     // 512

// ---------------------------------------------------------------------------
// Device scratch
// ---------------------------------------------------------------------------
__device__ __align__(16) u16   g_a2[TOK * 128];        // x1, fp16 single plane
__device__ __align__(16) u16   g_val[TOK * 128];       // value, fp16
__device__ __align__(16) float g_om[TOK * 64];         // offset/mask, fp32 (27 used, rest 0)
__device__ __align__(16) u16   g_dcn[TOK * 128];       // fp16 single
__device__ __align__(16) float g_op[TOK * 128];        // fp32 token-major

__device__ __align__(16) u16 g_w1h[128 * 128], g_w1l[128 * 128];   // fp16
__device__ __align__(16) u16 g_w2h[192 * 128], g_w2l[192 * 128];   // fp16
__device__ __align__(16) u16 g_w4h[128 * 128], g_w4l[128 * 128];   // fp16
__device__ __align__(16) u16 g_w5h[128 * 128], g_w5l[128 * 128];   // fp16
__device__ float g_bias0[128], g_bias1[128], g_bcat[192], g_zero[192];

// ---------------------------------------------------------------------------
// Helpers
// ---------------------------------------------------------------------------
DI uint32_t smem_u32(const void* p) {
    uint32_t a;
    asm("{ .reg .u64 t; cvta.to.shared.u64 t, %1; cvt.u32.u64 %0, t; }" : "=r"(a) : "l"(p));
    return a;
}

DI void cpa16(uint32_t dst, const void* src) {
    asm volatile("{ .reg .u64 g; cvta.to.global.u64 g, %1; "
                 "cp.async.cg.shared.global [%0], [g], 16; }"
                 :: "r"(dst), "l"(src));
}
DI void cpa_commit() { asm volatile("cp.async.commit_group;" ::: "memory"); }
DI void cpa_wait0() { asm volatile("cp.async.wait_group 0;" ::: "memory"); }
DI void cpa_wait1() { asm volatile("cp.async.wait_group 1;" ::: "memory"); }

DI void ldsm4(uint32_t (&r)[4], uint32_t addr) {
    asm volatile("ldmatrix.sync.aligned.m8n8.x4.shared.b16 {%0,%1,%2,%3}, [%4];"
                 : "=r"(r[0]), "=r"(r[1]), "=r"(r[2]), "=r"(r[3]) : "r"(addr));
}

DI void mma_f16(float (&d)[4], const uint32_t (&a)[4], uint32_t b0, uint32_t b1) {
    asm volatile("mma.sync.aligned.m16n8k16.row.col.f32.f16.f16.f32 "
                 "{%0,%1,%2,%3}, {%4,%5,%6,%7}, {%8,%9}, {%0,%1,%2,%3};"
                 : "+f"(d[0]), "+f"(d[1]), "+f"(d[2]), "+f"(d[3])
                 : "r"(a[0]), "r"(a[1]), "r"(a[2]), "r"(a[3]), "r"(b0), "r"(b1));
}

// XOR-swizzled 16-bit tile: row stride 256 B (128 elems), 16B chunk c -> c ^ (row&7)
DI uint32_t tile_off(int r, int chunk) { return (uint32_t)(r * 256 + ((chunk ^ (r & 7)) << 4)); }

DI uint32_t cvtf16x2(float f0, float f1) {             // {hi=f1, lo=f0}
    uint32_t r;
    asm("cvt.rn.f16x2.f32 %0, %1, %2;" : "=r"(r) : "f"(f1), "f"(f0));
    return r;
}

// ---------------------------------------------------------------------------
// Merged prep: fold BN, transpose to [n][k], split all weights to fp16 hi/lo
// (exact two-term split), plus biases.
// ---------------------------------------------------------------------------
__global__ void prep_all(const float* __restrict__ w_pw0, const float* __restrict__ w_pw1,
                         const float* __restrict__ w_vp,  const float* __restrict__ w_om,
                         const float* __restrict__ w_op,
                         const float* __restrict__ bn1_g, const float* __restrict__ bn1_b,
                         const float* __restrict__ bn1_m, const float* __restrict__ bn1_v,
                         const float* __restrict__ bn2_g, const float* __restrict__ bn2_b,
                         const float* __restrict__ bn2_m, const float* __restrict__ bn2_v,
                         const float* __restrict__ b_vp,  const float* __restrict__ b_om)
{
    int idx = blockIdx.x * blockDim.x + threadIdx.x;
    if (idx < 73728) {
        float w; u16 *H, *L; int off;
        if (idx < 16384) {                       // pw0 * BN1
            int k = idx & 127;
            w = w_pw0[idx] * bn1_g[k] * rsqrtf(bn1_v[k] + EPS);
            H = g_w1h; L = g_w1l; off = idx;
        } else if (idx < 32768) {                // pw1 * BN2
            int j = idx - 16384; int k = j & 127;
            w = w_pw1[j] * bn2_g[k] * rsqrtf(bn2_v[k] + EPS);
            H = g_w5h; L = g_w5l; off = j;
        } else if (idx < 49152) {                // w_op^T
            int j = idx - 32768; int n = j >> 7, k = j & 127;
            w = w_op[k * 128 + n];
            H = g_w4h; L = g_w4l; off = j;
        } else {                                 // [w_vp|w_om]^T padded to 192
            int j = idx - 49152; int n = j >> 7, k = j & 127;
            w = (n < 128) ? w_vp[k * 128 + n] : ((n < 155) ? w_om[k * 32 + (n - 128)] : 0.f);
            H = g_w2h; L = g_w2l; off = j;
        }
        __half h = __float2half_rn(w);
        H[off] = __half_as_ushort(h);
        L[off] = __half_as_ushort(__float2half_rn(w - __half2float(h)));
    } else if (idx < 73856) {
        int o = idx - 73728;
        float s = 0.f;
        for (int c = 0; c < 128; ++c) {
            float sc = bn1_g[c] * rsqrtf(bn1_v[c] + EPS);
            s += w_pw0[o * 128 + c] * (bn1_b[c] - bn1_m[c] * sc);
        }
        g_bias0[o] = s;
    } else if (idx < 73984) {
        int o = idx - 73856;
        float s = 0.f;
        for (int c = 0; c < 128; ++c) {
            float sc = bn2_g[c] * rsqrtf(bn2_v[c] + EPS);
            s += w_pw1[o * 128 + c] * (bn2_b[c] - bn2_m[c] * sc);
        }
        g_bias1[o] = s;
    } else if (idx < 74176) {
        int j = idx - 73984;
        g_bcat[j] = (j < 128) ? b_vp[j] : ((j < 155) ? b_om[j - 128] : 0.f);
        g_zero[j] = 0.f;
    }
}

// ---------------------------------------------------------------------------
// Persistent chunk-loop HMMA GEMM (fp16 2-pass: A single fp16, B exact
// fp16 hi/lo split; fp32 accum).
//  AKM=true : A read fp32 k-major (NCHW raw view); frags via LDS + cvt.
// MODE 0: fp32 row-major reg stores (token-major, ldo)
// MODE 1: raw-reshape scatter (B,C,HW)->(B,HW,C), fp16 single plane out
// MODE 2: fp32 NCHW final output
// MODE 3: split store (N=192): cols 0-127 -> fp16 outH (ld 128);
//         cols 128-191 -> fp32 outF (ld 64). Direct register stores.
// 8 warps = 2m(32) x 4n(N/4); CH=64 chunks, cp.async double buffer.
// ---------------------------------------------------------------------------
template<int N, int MODE, bool AKM>
__global__ void __launch_bounds__(256, 1)
gemm_mma(const float* __restrict__ Af, const u16* __restrict__ A0,
         const u16* __restrict__ B0, const u16* __restrict__ B1,
         const float* __restrict__ biasj,
         float* __restrict__ outF, int ldo, u16* __restrict__ outH)
{
    constexpr int NW = N / 4;
    constexpr int NT = NW / 8;
    constexpr int NP = NW / 16;
    constexpr int BOFF = 2 * N * 256;
    constexpr int ABUF = AKM ? (128 * 272) : (CH * 256);
    constexpr int ldp = N + 1;

    extern __shared__ char sm[];
    const uint32_t uSM = smem_u32(sm);
    const uint32_t uBh = uSM, uBl = uSM + N * 256;
    float* stage = (float*)(sm + BOFF + 2 * ABUF);

    const int t = threadIdx.x, w = t >> 5, l = t & 31;
    const int wm = w & 1, wn = w >> 1;
    const int nb0 = wn * NW;

    const int cbase = (l & 3) * 2;
    float bj0[NT], bj1[NT];
#pragma unroll
    for (int nt = 0; nt < NT; nt++) {
        int col = nb0 + nt * 8 + cbase;
        bj0[nt] = biasj[col];
        bj1[nt] = biasj[col + 1];
    }

    // B load (once)
    {
        const uint4* sh_ = (const uint4*)B0;
        const uint4* sl_ = (const uint4*)B1;
        for (int i = t; i < N * 16; i += 256) {
            int r = i >> 4, c = i & 15;
            uint32_t o = tile_off(r, c);
            cpa16(uBh + o, sh_ + i);
            cpa16(uBl + o, sl_ + i);
        }
    }
    cpa_commit();

    auto loadA = [&](uint32_t dst, int cid_) {
        size_t m0 = (size_t)cid_ * CH;
        if constexpr (AKM) {
            const float* base = Af + (m0 >> 12) * 524288 + (m0 & 4095);
            for (int i = t; i < 2048; i += 256) {
                int k = i >> 4, u = i & 15;
                cpa16(dst + (uint32_t)(k * 272 + u * 16), base + (size_t)k * 4096 + u * 4);
            }
        } else {
            const uint4* s0 = (const uint4*)(A0 + m0 * 128);
            for (int i = t; i < 1024; i += 256) {
                int r = i >> 4, c = i & 15;
                cpa16(dst + tile_off(r, c), s0 + i);
            }
        }
    };

    int cid = blockIdx.x;
    loadA(uSM + BOFF, cid);
    cpa_commit();

    const int arow_lo = wm * 32 + (l & 15);
    const int akhalf = l >> 4;
    const int brow_off = (l & 7) + ((l & 16) >> 1);
    const int bkhalf = (l >> 3) & 1;
    const int mfrag = wm * 32 + (l >> 2);
    const int kfrag = (l & 3) * 2;

    int p = 0;
    while (cid < CHUNKS) {
        const int nxt = cid + (int)gridDim.x;
        const bool hasnext = nxt < CHUNKS;
        if (hasnext) {
            loadA(uSM + BOFF + (p ^ 1) * ABUF, nxt);
            cpa_commit();
            cpa_wait1();
        } else {
            cpa_wait0();
        }
        __syncthreads();

        const uint32_t uA = uSM + BOFF + p * ABUF;
        const float* tileA = (const float*)(sm + BOFF + p * ABUF);

        float d[2][NT][4];
#pragma unroll
        for (int mt = 0; mt < 2; mt++)
#pragma unroll
            for (int nt = 0; nt < NT; nt++)
#pragma unroll
                for (int i = 0; i < 4; i++) d[mt][nt][i] = 0.f;

#pragma unroll
        for (int ks = 0; ks < 8; ks++) {
            uint32_t bh[NP][4], bl[NP][4];
#pragma unroll
            for (int np = 0; np < NP; np++) {
                uint32_t off = tile_off(nb0 + np * 16 + brow_off, 2 * ks + bkhalf);
                ldsm4(bh[np], uBh + off);
                ldsm4(bl[np], uBl + off);
            }
            uint32_t a[2][4];
            if constexpr (AKM) {
#pragma unroll
                for (int mt = 0; mt < 2; mt++) {
                    int mlo = mfrag + mt * 16;
                    int k0 = ks * 16 + kfrag;
                    a[mt][0] = cvtf16x2(tileA[(k0    ) * 68 + mlo],
                                        tileA[(k0 + 1) * 68 + mlo]);
                    a[mt][1] = cvtf16x2(tileA[(k0    ) * 68 + mlo + 8],
                                        tileA[(k0 + 1) * 68 + mlo + 8]);
                    a[mt][2] = cvtf16x2(tileA[(k0 + 8) * 68 + mlo],
                                        tileA[(k0 + 9) * 68 + mlo]);
                    a[mt][3] = cvtf16x2(tileA[(k0 + 8) * 68 + mlo + 8],
                                        tileA[(k0 + 9) * 68 + mlo + 8]);
                }
            } else {
#pragma unroll
                for (int mt = 0; mt < 2; mt++)
                    ldsm4(a[mt], uA + tile_off(arow_lo + mt * 16, 2 * ks + akhalf));
            }
            // pass 1: A*Bh
#pragma unroll
            for (int np = 0; np < NP; np++)
#pragma unroll
                for (int mt = 0; mt < 2; mt++) {
                    mma_f16(d[mt][2 * np],     a[mt], bh[np][0], bh[np][1]);
                    mma_f16(d[mt][2 * np + 1], a[mt], bh[np][2], bh[np][3]);
                }
            // pass 2: A*Bl
#pragma unroll
            for (int np = 0; np < NP; np++)
#pragma unroll
                for (int mt = 0; mt < 2; mt++) {
                    mma_f16(d[mt][2 * np],     a[mt], bl[np][0], bl[np][1]);
                    mma_f16(d[mt][2 * np + 1], a[mt], bl[np][2], bl[np][3]);
                }
        }

        const size_t m0 = (size_t)cid * CH;
        const int rloc = wm * 32 + (l >> 2);

        if (MODE == 0) {
#pragma unroll
            for (int mt = 0; mt < 2; mt++)
#pragma unroll
                for (int nt = 0; nt < NT; nt++) {
                    int row = rloc + mt * 16;
                    int col = nb0 + nt * 8 + cbase;
                    float2 v0 = make_float2(d[mt][nt][0] + bj0[nt], d[mt][nt][1] + bj1[nt]);
                    float2 v1 = make_float2(d[mt][nt][2] + bj0[nt], d[mt][nt][3] + bj1[nt]);
                    *(float2*)(outF + (m0 + row) * (size_t)ldo + col) = v0;
                    *(float2*)(outF + (m0 + row + 8) * (size_t)ldo + col) = v1;
                }
        } else if (MODE == 3) {
            // split: cols<128 -> fp16 outH (ld 128); cols>=128 -> fp32 outF (ld 64)
#pragma unroll
            for (int mt = 0; mt < 2; mt++)
#pragma unroll
                for (int nt = 0; nt < NT; nt++) {
                    int row = rloc + mt * 16;
                    int col = nb0 + nt * 8 + cbase;
                    float v0 = d[mt][nt][0] + bj0[nt], v1 = d[mt][nt][1] + bj1[nt];
                    float v2 = d[mt][nt][2] + bj0[nt], v3 = d[mt][nt][3] + bj1[nt];
                    if (col < 128) {
                        *(uint32_t*)(outH + (m0 + row) * 128 + col)     = cvtf16x2(v0, v1);
                        *(uint32_t*)(outH + (m0 + row + 8) * 128 + col) = cvtf16x2(v2, v3);
                    } else {
                        *(float2*)(outF + (m0 + row) * 64 + (col - 128))     = make_float2(v0, v1);
                        *(float2*)(outF + (m0 + row + 8) * 64 + (col - 128)) = make_float2(v2, v3);
                    }
                }
        } else {
#pragma unroll
            for (int mt = 0; mt < 2; mt++)
#pragma unroll
                for (int nt = 0; nt < NT; nt++) {
                    int row = rloc + mt * 16;
                    int col = nb0 + nt * 8 + cbase;
                    stage[row * ldp + col]           = d[mt][nt][0] + bj0[nt];
                    stage[row * ldp + col + 1]       = d[mt][nt][1] + bj1[nt];
                    stage[(row + 8) * ldp + col]     = d[mt][nt][2] + bj0[nt];
                    stage[(row + 8) * ldp + col + 1] = d[mt][nt][3] + bj1[nt];
                }
            __syncthreads();
            if (MODE == 1) {
                const int b  = (int)(m0 >> 12);
                const int sh = (int)((m0 & 4095) >> 7);
                const int cb = (int)(m0 & 64);
                for (int i = t; i < N * 16; i += 256) {
                    int n = i >> 4, q = i & 15, j0 = q * 4;
                    float v0 = stage[(j0 + 0) * ldp + n], v1 = stage[(j0 + 1) * ldp + n];
                    float v2 = stage[(j0 + 2) * ldp + n], v3 = stage[(j0 + 3) * ldp + n];
                    size_t row = (size_t)b * 4096 + (size_t)n * 32 + sh;
                    uint2 o;
                    o.x = cvtf16x2(v0, v1);
                    o.y = cvtf16x2(v2, v3);
                    ((uint2*)(outH + row * 128 + cb))[q] = o;
                }
            } else {
                const int b  = (int)(m0 >> 12);
                const int s0 = (int)(m0 & 4095);
                for (int i = t; i < N * 16; i += 256) {
                    int n = i >> 4, q = i & 15, j0 = q * 4;
                    float4 v = make_float4(stage[(j0 + 0) * ldp + n], stage[(j0 + 1) * ldp + n],
                                           stage[(j0 + 2) * ldp + n], stage[(j0 + 3) * ldp + n]);
                    *(float4*)(outF + (size_t)b * 524288 + (size_t)n * 4096 + s0 + j0) = v;
                }
            }
        }
        __syncthreads();
        p ^= 1;
        cid = nxt;
    }
}

// ---------------------------------------------------------------------------
// DCNv4 core v5b — two positions per warp, uint4 gathers, half2 interp.
// Same as R14 but WITHOUT the min-blocks launch bound that capped regs at 32
// and caused local-memory spills (DRAM 17.7%). Registers free to ~56.
// ---------------------------------------------------------------------------
__global__ void __launch_bounds__(256)
dcn_kernel(const u16* __restrict__ val, const float* __restrict__ om,
           u16* __restrict__ oh)
{
    const int warp = threadIdx.x >> 5;
    const int lane = threadIdx.x & 31;
    const int half = lane >> 4;
    const int hl   = lane & 15;
    const int pos  = blockIdx.x * 16 + warp * 2 + half;   // 16-aligned: no batch straddle
    const int b = pos >> 12;
    const int s = pos & 4095;
    const int h = s >> 6;
    const int w = s & 63;

    // --- setup: lanes hl 0..8 meaningful; 9..15 compute harmless clamped data ---
    uint32_t wb00, wb10, wb01, wb11;
    int      o00, o10, o01, o11;
    {
        const int k = hl;                        // om cols 27..63 are exact zeros
        const float* omp = om + (size_t)pos * 64 + 3 * min(k, 15);
        float dx = omp[0], dy = omp[1], m = omp[2];
        int ky = k / 3, kx = k - ky * 3;
        float px = (float)(w + kx - 1) + dx;
        float py = (float)(h + ky - 1) + dy;
        float xf = floorf(px), yf = floorf(py);
        float fx = px - xf, fy = py - yf;
        int x0 = (int)xf, y0 = (int)yf;
        int x1 = x0 + 1,  y1 = y0 + 1;
        float vx0 = (x0 >= 0 && x0 < 64) ? m : 0.f;
        float vx1 = (x1 >= 0 && x1 < 64) ? m : 0.f;
        float gy0 = (y0 >= 0 && y0 < 64) ? 1.f : 0.f;
        float gy1 = (y1 >= 0 && y1 < 64) ? 1.f : 0.f;
        float gx0 = 1.f - fx, gy0f = 1.f - fy;
        float w00 = gx0 * gy0f * vx0 * gy0;
        float w10 = fx  * gy0f * vx1 * gy0;
        float w01 = gx0 * fy   * vx0 * gy1;
        float w11 = fx  * fy   * vx1 * gy1;
        wb00 = cvtf16x2(w00, w00);
        wb10 = cvtf16x2(w10, w10);
        wb01 = cvtf16x2(w01, w01);
        wb11 = cvtf16x2(w11, w11);
        int xc0 = min(max(x0, 0), 63), xc1 = min(max(x1, 0), 63);
        int yc0 = min(max(y0, 0), 63), yc1 = min(max(y1, 0), 63);
        o00 = (yc0 * 64 + xc0) * 128;
        o10 = (yc0 * 64 + xc1) * 128;
        o01 = (yc1 * 64 + xc0) * 128;
        o11 = (yc1 * 64 + xc1) * 128;
    }

    const u16* vbc = val + (((size_t)b << 12) * 128) + (hl << 3);
    float acc[8];
#pragma unroll
    for (int i = 0; i < 8; i++) acc[i] = 0.f;
    const unsigned FULL = 0xffffffffu;
    const int sbase = lane & 16;

#pragma unroll
    for (int k = 0; k < 9; ++k) {
        const int src = sbase | k;
        int a0 = __shfl_sync(FULL, o00, src);
        int a1 = __shfl_sync(FULL, o10, src);
        int a2 = __shfl_sync(FULL, o01, src);
        int a3 = __shfl_sync(FULL, o11, src);
        uint32_t u0 = __shfl_sync(FULL, wb00, src);
        uint32_t u1 = __shfl_sync(FULL, wb10, src);
        uint32_t u2 = __shfl_sync(FULL, wb01, src);
        uint32_t u3 = __shfl_sync(FULL, wb11, src);
        uint4 r0 = *(const uint4*)(vbc + a0);
        uint4 r1 = *(const uint4*)(vbc + a1);
        uint4 r2 = *(const uint4*)(vbc + a2);
        uint4 r3 = *(const uint4*)(vbc + a3);
        __half2 h0 = *(__half2*)&u0, h1 = *(__half2*)&u1;
        __half2 h2 = *(__half2*)&u2, h3 = *(__half2*)&u3;
        __half2 pa = __hmul2(h0, *(__half2*)&r0.x);
        __half2 pb = __hmul2(h0, *(__half2*)&r0.y);
        __half2 pc = __hmul2(h0, *(__half2*)&r0.z);
        __half2 pd = __hmul2(h0, *(__half2*)&r0.w);
        pa = __hfma2(h1, *(__half2*)&r1.x, pa);
        pb = __hfma2(h1, *(__half2*)&r1.y, pb);
        pc = __hfma2(h1, *(__half2*)&r1.z, pc);
        pd = __hfma2(h1, *(__half2*)&r1.w, pd);
        pa = __hfma2(h2, *(__half2*)&r2.x, pa);
        pb = __hfma2(h2, *(__half2*)&r2.y, pb);
        pc = __hfma2(h2, *(__half2*)&r2.z, pc);
        pd = __hfma2(h2, *(__half2*)&r2.w, pd);
        pa = __hfma2(h3, *(__half2*)&r3.x, pa);
        pb = __hfma2(h3, *(__half2*)&r3.y, pb);
        pc = __hfma2(h3, *(__half2*)&r3.z, pc);
        pd = __hfma2(h3, *(__half2*)&r3.w, pd);
        float2 fa = __half22float2(pa);
        float2 fb = __half22float2(pb);
        float2 fc = __half22float2(pc);
        float2 fd = __half22float2(pd);
        acc[0] += fa.x; acc[1] += fa.y; acc[2] += fb.x; acc[3] += fb.y;
        acc[4] += fc.x; acc[5] += fc.y; acc[6] += fd.x; acc[7] += fd.y;
    }
    uint4 o;
    o.x = cvtf16x2(acc[0], acc[1]);
    o.y = cvtf16x2(acc[2], acc[3]);
    o.z = cvtf16x2(acc[4], acc[5]);
    o.w = cvtf16x2(acc[6], acc[7]);
    *(uint4*)(oh + (size_t)pos * 128 + (hl << 3)) = o;
}

// ---------------------------------------------------------------------------
// Launcher
// ---------------------------------------------------------------------------
extern "C" void kernel_launch(void* const* d_in, const int* in_sizes, int n_in,
                              void* d_out, int out_size)
{
    (void)in_sizes; (void)n_in; (void)out_size;
    const float* x     = (const float*)d_in[0];
    const float* bn1_g = (const float*)d_in[1];
    const float* bn1_b = (const float*)d_in[2];
    const float* bn1_m = (const float*)d_in[3];
    const float* bn1_v = (const float*)d_in[4];
    const float* w_pw0 = (const float*)d_in[5];
    const float* w_vp  = (const float*)d_in[6];
    const float* b_vp  = (const float*)d_in[7];
    const float* w_om  = (const float*)d_in[8];
    const float* b_om  = (const float*)d_in[9];
    const float* w_op  = (const float*)d_in[10];
    const float* bn2_g = (const float*)d_in[11];
    const float* bn2_b = (const float*)d_in[12];
    const float* bn2_m = (const float*)d_in[13];
    const float* bn2_v = (const float*)d_in[14];
    const float* w_pw1 = (const float*)d_in[15];
    float* out = (float*)d_out;

    u16 *a2, *val, *dcn;
    u16 *w1h, *w1l, *w2h, *w2l, *w4h, *w4l, *w5h, *w5l;
    float *omb, *op, *bias0, *bias1, *bcat, *zero;
    cudaGetSymbolAddress((void**)&a2, g_a2);
    cudaGetSymbolAddress((void**)&val, g_val);    cudaGetSymbolAddress((void**)&omb, g_om);
    cudaGetSymbolAddress((void**)&dcn, g_dcn);    cudaGetSymbolAddress((void**)&op, g_op);
    cudaGetSymbolAddress((void**)&w1h, g_w1h);    cudaGetSymbolAddress((void**)&w1l, g_w1l);
    cudaGetSymbolAddress((void**)&w2h, g_w2h);    cudaGetSymbolAddress((void**)&w2l, g_w2l);
    cudaGetSymbolAddress((void**)&w4h, g_w4h);    cudaGetSymbolAddress((void**)&w4l, g_w4l);
    cudaGetSymbolAddress((void**)&w5h, g_w5h);    cudaGetSymbolAddress((void**)&w5l, g_w5l);
    cudaGetSymbolAddress((void**)&bias0, g_bias0); cudaGetSymbolAddress((void**)&bias1, g_bias1);
    cudaGetSymbolAddress((void**)&bcat, g_bcat);  cudaGetSymbolAddress((void**)&zero, g_zero);

    const int SM_G1 = 65536 + 2 * 128 * 272 + 64 * 129 * 4;
    const int SM_G2 = 98304 + 2 * 64 * 256;
    const int SM_G4 = 65536 + 2 * 64 * 256;
    const int SM_G5 = 65536 + 2 * 128 * 272 + 64 * 129 * 4;
    cudaFuncSetAttribute((const void*)gemm_mma<128, 1, true>,
                         cudaFuncAttributeMaxDynamicSharedMemorySize, SM_G1);
    cudaFuncSetAttribute((const void*)gemm_mma<192, 3, false>,
                         cudaFuncAttributeMaxDynamicSharedMemorySize, SM_G2);
    cudaFuncSetAttribute((const void*)gemm_mma<128, 0, false>,
                         cudaFuncAttributeMaxDynamicSharedMemorySize, SM_G4);
    cudaFuncSetAttribute((const void*)gemm_mma<128, 2, true>,
                         cudaFuncAttributeMaxDynamicSharedMemorySize, SM_G5);

    const int GRID = 148;

    prep_all<<<290, 256>>>(w_pw0, w_pw1, w_vp, w_om, w_op,
                           bn1_g, bn1_b, bn1_m, bn1_v,
                           bn2_g, bn2_b, bn2_m, bn2_v, b_vp, b_om);

    // 1) x1 = x(NCHW fp32 k-major) @ w1^T + bias0 -> fp16 single scatter
    gemm_mma<128, 1, true><<<GRID, 256, SM_G1>>>(
        x, nullptr, w1h, w1l, bias0, nullptr, 0, a2);

    // 2) vpom split: value -> fp16 g_val, offset/mask -> fp32 g_om (ld 64)
    gemm_mma<192, 3, false><<<GRID, 256, SM_G2>>>(
        nullptr, a2, w2h, w2l, bcat, omb, 0, val);

    // 3) DCNv4 core (2 positions/warp, uint4 fp16 gathers) -> fp16 plane
    dcn_kernel<<<2048, 256>>>(val, omb, dcn);

    // 4) op = dcn @ w_op -> fp32 token-major (the NCHW raw view for step 5)
    gemm_mma<128, 0, false><<<GRID, 256, SM_G4>>>(
        nullptr, dcn, w4h, w4l, zero, op, 128, nullptr);

    // 5) out = (BN2-folded pw1) @ op(NCHW view, fp32 k-major read) -> fp32 NCHW
    gemm_mma<128, 2, true><<<GRID, 256, SM_G5>>>(
        op, nullptr, w5h, w5l, bias1, out, 0, nullptr);
}

// round 16
// speedup vs baseline: 1.2035x; 1.0235x over previous
#include <cuda_runtime.h>
#include <cuda_bf16.h>
#include <cuda_fp16.h>
#include <cstdint>
#include <math.h>

#define DI __device__ __forceinline__
typedef unsigned short u16;

constexpr int TOK = 32768;           // 8 * 64 * 64
constexpr float EPS = 1e-5f;
constexpr int CH = 64;               // tokens per chunk
constexpr int CHUNKS = TOK / CH;     // 512

// ---------------------------------------------------------------------------
// Device scratch
// ---------------------------------------------------------------------------
__device__ __align__(16) u16   g_a2[TOK * 128];        // x1, fp16 single plane
__device__ __align__(16) u16   g_val[TOK * 128];       // value, fp16
__device__ __align__(16) float g_om[TOK * 64];         // offset/mask, fp32 (27 used, rest 0)
__device__ __align__(16) u16   g_dcn[TOK * 128];       // fp16 single
__device__ __align__(16) float g_op[TOK * 128];        // fp32 token-major

__device__ __align__(16) u16 g_w1h[128 * 128], g_w1l[128 * 128];   // fp16
__device__ __align__(16) u16 g_w2h[192 * 128], g_w2l[192 * 128];   // fp16 (lo used rows 128+)
__device__ __align__(16) u16 g_w4h[128 * 128];                      // fp16 (single)
__device__ __align__(16) u16 g_w5h[128 * 128], g_w5l[128 * 128];   // fp16
__device__ float g_bias0[128], g_bias1[128], g_bcat[192], g_zero[192];

// ---------------------------------------------------------------------------
// Helpers
// ---------------------------------------------------------------------------
DI uint32_t smem_u32(const void* p) {
    uint32_t a;
    asm("{ .reg .u64 t; cvta.to.shared.u64 t, %1; cvt.u32.u64 %0, t; }" : "=r"(a) : "l"(p));
    return a;
}

DI void cpa16(uint32_t dst, const void* src) {
    asm volatile("{ .reg .u64 g; cvta.to.global.u64 g, %1; "
                 "cp.async.cg.shared.global [%0], [g], 16; }"
                 :: "r"(dst), "l"(src));
}
DI void cpa_commit() { asm volatile("cp.async.commit_group;" ::: "memory"); }
DI void cpa_wait0() { asm volatile("cp.async.wait_group 0;" ::: "memory"); }
DI void cpa_wait1() { asm volatile("cp.async.wait_group 1;" ::: "memory"); }

DI void ldsm4(uint32_t (&r)[4], uint32_t addr) {
    asm volatile("ldmatrix.sync.aligned.m8n8.x4.shared.b16 {%0,%1,%2,%3}, [%4];"
                 : "=r"(r[0]), "=r"(r[1]), "=r"(r[2]), "=r"(r[3]) : "r"(addr));
}

DI void mma_f16(float (&d)[4], const uint32_t (&a)[4], uint32_t b0, uint32_t b1) {
    asm volatile("mma.sync.aligned.m16n8k16.row.col.f32.f16.f16.f32 "
                 "{%0,%1,%2,%3}, {%4,%5,%6,%7}, {%8,%9}, {%0,%1,%2,%3};"
                 : "+f"(d[0]), "+f"(d[1]), "+f"(d[2]), "+f"(d[3])
                 : "r"(a[0]), "r"(a[1]), "r"(a[2]), "r"(a[3]), "r"(b0), "r"(b1));
}

// XOR-swizzled 16-bit tile: row stride 256 B (128 elems), 16B chunk c -> c ^ (row&7)
DI uint32_t tile_off(int r, int chunk) { return (uint32_t)(r * 256 + ((chunk ^ (r & 7)) << 4)); }

DI uint32_t cvtf16x2(float f0, float f1) {             // {hi=f1, lo=f0}
    uint32_t r;
    asm("cvt.rn.f16x2.f32 %0, %1, %2;" : "=r"(r) : "f"(f1), "f"(f0));
    return r;
}

// ---------------------------------------------------------------------------
// Merged prep: fold BN, transpose to [n][k], fp16 hi/lo split, biases.
// ---------------------------------------------------------------------------
__global__ void prep_all(const float* __restrict__ w_pw0, const float* __restrict__ w_pw1,
                         const float* __restrict__ w_vp,  const float* __restrict__ w_om,
                         const float* __restrict__ w_op,
                         const float* __restrict__ bn1_g, const float* __restrict__ bn1_b,
                         const float* __restrict__ bn1_m, const float* __restrict__ bn1_v,
                         const float* __restrict__ bn2_g, const float* __restrict__ bn2_b,
                         const float* __restrict__ bn2_m, const float* __restrict__ bn2_v,
                         const float* __restrict__ b_vp,  const float* __restrict__ b_om)
{
    int idx = blockIdx.x * blockDim.x + threadIdx.x;
    if (idx < 73728) {
        float w; u16 *H, *L; int off;
        if (idx < 16384) {                       // pw0 * BN1 (hi/lo)
            int k = idx & 127;
            w = w_pw0[idx] * bn1_g[k] * rsqrtf(bn1_v[k] + EPS);
            H = g_w1h; L = g_w1l; off = idx;
        } else if (idx < 32768) {                // pw1 * BN2 (hi/lo)
            int j = idx - 16384; int k = j & 127;
            w = w_pw1[j] * bn2_g[k] * rsqrtf(bn2_v[k] + EPS);
            H = g_w5h; L = g_w5l; off = j;
        } else if (idx < 49152) {                // w_op^T (single hi)
            int j = idx - 32768; int n = j >> 7, k = j & 127;
            w = w_op[k * 128 + n];
            H = g_w4h; L = nullptr; off = j;
        } else {                                 // [w_vp|w_om]^T padded (hi; lo rows 128+)
            int j = idx - 49152; int n = j >> 7, k = j & 127;
            w = (n < 128) ? w_vp[k * 128 + n] : ((n < 155) ? w_om[k * 32 + (n - 128)] : 0.f);
            H = g_w2h; L = g_w2l; off = j;
        }
        __half h = __float2half_rn(w);
        H[off] = __half_as_ushort(h);
        if (L) L[off] = __half_as_ushort(__float2half_rn(w - __half2float(h)));
    } else if (idx < 73856) {
        int o = idx - 73728;
        float s = 0.f;
        for (int c = 0; c < 128; ++c) {
            float sc = bn1_g[c] * rsqrtf(bn1_v[c] + EPS);
            s += w_pw0[o * 128 + c] * (bn1_b[c] - bn1_m[c] * sc);
        }
        g_bias0[o] = s;
    } else if (idx < 73984) {
        int o = idx - 73856;
        float s = 0.f;
        for (int c = 0; c < 128; ++c) {
            float sc = bn2_g[c] * rsqrtf(bn2_v[c] + EPS);
            s += w_pw1[o * 128 + c] * (bn2_b[c] - bn2_m[c] * sc);
        }
        g_bias1[o] = s;
    } else if (idx < 74176) {
        int j = idx - 73984;
        g_bcat[j] = (j < 128) ? b_vp[j] : ((j < 155) ? b_om[j - 128] : 0.f);
        g_zero[j] = 0.f;
    }
}

// ---------------------------------------------------------------------------
// Persistent chunk-loop HMMA GEMM (fp16: A single fp16; B hi plane full,
// lo plane only for the last BLO rows (exact split there); fp32 accum).
//  AKM=true : A read fp32 k-major (NCHW raw view); frags via LDS + cvt.
// MODE 0: fp32 row-major reg stores | MODE 1: raw-reshape fp16 scatter
// MODE 2: fp32 NCHW final output    | MODE 3: split fp16/fp32 (N=192)
// BLO: rows [N-BLO, N) get the second (lo) B pass. BLO=N -> full 2-pass;
// BLO=0 -> single-pass. MINB: min blocks/SM for launch bounds.
// 8 warps = 2m(32) x 4n(N/4); CH=64 chunks, cp.async double buffer.
// ---------------------------------------------------------------------------
template<int N, int MODE, bool AKM, int BLO, int MINB>
__global__ void __launch_bounds__(256, MINB)
gemm_mma(const float* __restrict__ Af, const u16* __restrict__ A0,
         const u16* __restrict__ B0, const u16* __restrict__ B1,
         const float* __restrict__ biasj,
         float* __restrict__ outF, int ldo, u16* __restrict__ outH)
{
    constexpr int NW = N / 4;
    constexpr int NT = NW / 8;
    constexpr int NP = NW / 16;
    constexpr int BOFF = (N + BLO) * 256;
    constexpr int ABUF = AKM ? (128 * 272) : (CH * 256);
    constexpr int ldp = N + 1;
    constexpr int NLO = N - BLO;             // first row with a lo plane

    extern __shared__ char sm[];
    const uint32_t uSM = smem_u32(sm);
    const uint32_t uBh = uSM, uBl = uSM + N * 256;
    float* stage = (float*)(sm + BOFF + 2 * ABUF);

    const int t = threadIdx.x, w = t >> 5, l = t & 31;
    const int wm = w & 1, wn = w >> 1;
    const int nb0 = wn * NW;

    const int cbase = (l & 3) * 2;
    float bj0[NT], bj1[NT];
#pragma unroll
    for (int nt = 0; nt < NT; nt++) {
        int col = nb0 + nt * 8 + cbase;
        bj0[nt] = biasj[col];
        bj1[nt] = biasj[col + 1];
    }

    // B load (once). B1 points at row NLO of the lo plane.
    {
        const uint4* sh_ = (const uint4*)B0;
        for (int i = t; i < N * 16; i += 256) {
            int r = i >> 4, c = i & 15;
            cpa16(uBh + tile_off(r, c), sh_ + i);
        }
        if constexpr (BLO > 0) {
            const uint4* sl_ = (const uint4*)B1;
            for (int i = t; i < BLO * 16; i += 256) {
                int r = i >> 4, c = i & 15;
                cpa16(uBl + tile_off(r, c), sl_ + i);
            }
        }
    }
    cpa_commit();

    auto loadA = [&](uint32_t dst, int cid_) {
        size_t m0 = (size_t)cid_ * CH;
        if constexpr (AKM) {
            const float* base = Af + (m0 >> 12) * 524288 + (m0 & 4095);
            for (int i = t; i < 2048; i += 256) {
                int k = i >> 4, u = i & 15;
                cpa16(dst + (uint32_t)(k * 272 + u * 16), base + (size_t)k * 4096 + u * 4);
            }
        } else {
            const uint4* s0 = (const uint4*)(A0 + m0 * 128);
            for (int i = t; i < 1024; i += 256) {
                int r = i >> 4, c = i & 15;
                cpa16(dst + tile_off(r, c), s0 + i);
            }
        }
    };

    int cid = blockIdx.x;
    loadA(uSM + BOFF, cid);
    cpa_commit();

    const int arow_lo = wm * 32 + (l & 15);
    const int akhalf = l >> 4;
    const int brow_off = (l & 7) + ((l & 16) >> 1);
    const int bkhalf = (l >> 3) & 1;
    const int mfrag = wm * 32 + (l >> 2);
    const int kfrag = (l & 3) * 2;

    int p = 0;
    while (cid < CHUNKS) {
        const int nxt = cid + (int)gridDim.x;
        const bool hasnext = nxt < CHUNKS;
        if (hasnext) {
            loadA(uSM + BOFF + (p ^ 1) * ABUF, nxt);
            cpa_commit();
            cpa_wait1();
        } else {
            cpa_wait0();
        }
        __syncthreads();

        const uint32_t uA = uSM + BOFF + p * ABUF;
        const float* tileA = (const float*)(sm + BOFF + p * ABUF);

        float d[2][NT][4];
#pragma unroll
        for (int mt = 0; mt < 2; mt++)
#pragma unroll
            for (int nt = 0; nt < NT; nt++)
#pragma unroll
                for (int i = 0; i < 4; i++) d[mt][nt][i] = 0.f;

#pragma unroll
        for (int ks = 0; ks < 8; ks++) {
            uint32_t bh[NP][4];
#pragma unroll
            for (int np = 0; np < NP; np++)
                ldsm4(bh[np], uBh + tile_off(nb0 + np * 16 + brow_off, 2 * ks + bkhalf));
            uint32_t a[2][4];
            if constexpr (AKM) {
#pragma unroll
                for (int mt = 0; mt < 2; mt++) {
                    int mlo = mfrag + mt * 16;
                    int k0 = ks * 16 + kfrag;
                    a[mt][0] = cvtf16x2(tileA[(k0    ) * 68 + mlo],
                                        tileA[(k0 + 1) * 68 + mlo]);
                    a[mt][1] = cvtf16x2(tileA[(k0    ) * 68 + mlo + 8],
                                        tileA[(k0 + 1) * 68 + mlo + 8]);
                    a[mt][2] = cvtf16x2(tileA[(k0 + 8) * 68 + mlo],
                                        tileA[(k0 + 9) * 68 + mlo]);
                    a[mt][3] = cvtf16x2(tileA[(k0 + 8) * 68 + mlo + 8],
                                        tileA[(k0 + 9) * 68 + mlo + 8]);
                }
            } else {
#pragma unroll
                for (int mt = 0; mt < 2; mt++)
                    ldsm4(a[mt], uA + tile_off(arow_lo + mt * 16, 2 * ks + akhalf));
            }
            // pass 1: A * Bh (all columns)
#pragma unroll
            for (int np = 0; np < NP; np++)
#pragma unroll
                for (int mt = 0; mt < 2; mt++) {
                    mma_f16(d[mt][2 * np],     a[mt], bh[np][0], bh[np][1]);
                    mma_f16(d[mt][2 * np + 1], a[mt], bh[np][2], bh[np][3]);
                }
            // pass 2: A * Bl (only column tiles >= NLO)
            if constexpr (BLO > 0) {
#pragma unroll
                for (int np = 0; np < NP; np++) {
                    if (NLO == 0 || nb0 + np * 16 >= NLO) {
                        uint32_t bl[4];
                        ldsm4(bl, uBl + tile_off(nb0 + np * 16 - NLO + brow_off,
                                                 2 * ks + bkhalf));
#pragma unroll
                        for (int mt = 0; mt < 2; mt++) {
                            mma_f16(d[mt][2 * np],     a[mt], bl[0], bl[1]);
                            mma_f16(d[mt][2 * np + 1], a[mt], bl[2], bl[3]);
                        }
                    }
                }
            }
        }

        const size_t m0 = (size_t)cid * CH;
        const int rloc = wm * 32 + (l >> 2);

        if (MODE == 0) {
#pragma unroll
            for (int mt = 0; mt < 2; mt++)
#pragma unroll
                for (int nt = 0; nt < NT; nt++) {
                    int row = rloc + mt * 16;
                    int col = nb0 + nt * 8 + cbase;
                    float2 v0 = make_float2(d[mt][nt][0] + bj0[nt], d[mt][nt][1] + bj1[nt]);
                    float2 v1 = make_float2(d[mt][nt][2] + bj0[nt], d[mt][nt][3] + bj1[nt]);
                    *(float2*)(outF + (m0 + row) * (size_t)ldo + col) = v0;
                    *(float2*)(outF + (m0 + row + 8) * (size_t)ldo + col) = v1;
                }
        } else if (MODE == 3) {
            // split: cols<128 -> fp16 outH (ld 128); cols>=128 -> fp32 outF (ld 64)
#pragma unroll
            for (int mt = 0; mt < 2; mt++)
#pragma unroll
                for (int nt = 0; nt < NT; nt++) {
                    int row = rloc + mt * 16;
                    int col = nb0 + nt * 8 + cbase;
                    float v0 = d[mt][nt][0] + bj0[nt], v1 = d[mt][nt][1] + bj1[nt];
                    float v2 = d[mt][nt][2] + bj0[nt], v3 = d[mt][nt][3] + bj1[nt];
                    if (col < 128) {
                        *(uint32_t*)(outH + (m0 + row) * 128 + col)     = cvtf16x2(v0, v1);
                        *(uint32_t*)(outH + (m0 + row + 8) * 128 + col) = cvtf16x2(v2, v3);
                    } else {
                        *(float2*)(outF + (m0 + row) * 64 + (col - 128))     = make_float2(v0, v1);
                        *(float2*)(outF + (m0 + row + 8) * 64 + (col - 128)) = make_float2(v2, v3);
                    }
                }
        } else {
#pragma unroll
            for (int mt = 0; mt < 2; mt++)
#pragma unroll
                for (int nt = 0; nt < NT; nt++) {
                    int row = rloc + mt * 16;
                    int col = nb0 + nt * 8 + cbase;
                    stage[row * ldp + col]           = d[mt][nt][0] + bj0[nt];
                    stage[row * ldp + col + 1]       = d[mt][nt][1] + bj1[nt];
                    stage[(row + 8) * ldp + col]     = d[mt][nt][2] + bj0[nt];
                    stage[(row + 8) * ldp + col + 1] = d[mt][nt][3] + bj1[nt];
                }
            __syncthreads();
            if (MODE == 1) {
                const int b  = (int)(m0 >> 12);
                const int sh = (int)((m0 & 4095) >> 7);
                const int cb = (int)(m0 & 64);
                for (int i = t; i < N * 16; i += 256) {
                    int n = i >> 4, q = i & 15, j0 = q * 4;
                    float v0 = stage[(j0 + 0) * ldp + n], v1 = stage[(j0 + 1) * ldp + n];
                    float v2 = stage[(j0 + 2) * ldp + n], v3 = stage[(j0 + 3) * ldp + n];
                    size_t row = (size_t)b * 4096 + (size_t)n * 32 + sh;
                    uint2 o;
                    o.x = cvtf16x2(v0, v1);
                    o.y = cvtf16x2(v2, v3);
                    ((uint2*)(outH + row * 128 + cb))[q] = o;
                }
            } else {
                const int b  = (int)(m0 >> 12);
                const int s0 = (int)(m0 & 4095);
                for (int i = t; i < N * 16; i += 256) {
                    int n = i >> 4, q = i & 15, j0 = q * 4;
                    float4 v = make_float4(stage[(j0 + 0) * ldp + n], stage[(j0 + 1) * ldp + n],
                                           stage[(j0 + 2) * ldp + n], stage[(j0 + 3) * ldp + n]);
                    *(float4*)(outF + (size_t)b * 524288 + (size_t)n * 4096 + s0 + j0) = v;
                }
            }
        }
        __syncthreads();
        p ^= 1;
        cid = nxt;
    }
}

// ---------------------------------------------------------------------------
// DCNv4 core v5b — two positions per warp, uint4 gathers, half2 interp.
// ---------------------------------------------------------------------------
__global__ void __launch_bounds__(256)
dcn_kernel(const u16* __restrict__ val, const float* __restrict__ om,
           u16* __restrict__ oh)
{
    const int warp = threadIdx.x >> 5;
    const int lane = threadIdx.x & 31;
    const int half = lane >> 4;
    const int hl   = lane & 15;
    const int pos  = blockIdx.x * 16 + warp * 2 + half;
    const int b = pos >> 12;
    const int s = pos & 4095;
    const int h = s >> 6;
    const int w = s & 63;

    uint32_t wb00, wb10, wb01, wb11;
    int      o00, o10, o01, o11;
    {
        const int k = hl;                        // om cols 27..63 are exact zeros
        const float* omp = om + (size_t)pos * 64 + 3 * min(k, 15);
        float dx = omp[0], dy = omp[1], m = omp[2];
        int ky = k / 3, kx = k - ky * 3;
        float px = (float)(w + kx - 1) + dx;
        float py = (float)(h + ky - 1) + dy;
        float xf = floorf(px), yf = floorf(py);
        float fx = px - xf, fy = py - yf;
        int x0 = (int)xf, y0 = (int)yf;
        int x1 = x0 + 1,  y1 = y0 + 1;
        float vx0 = (x0 >= 0 && x0 < 64) ? m : 0.f;
        float vx1 = (x1 >= 0 && x1 < 64) ? m : 0.f;
        float gy0 = (y0 >= 0 && y0 < 64) ? 1.f : 0.f;
        float gy1 = (y1 >= 0 && y1 < 64) ? 1.f : 0.f;
        float gx0 = 1.f - fx, gy0f = 1.f - fy;
        float w00 = gx0 * gy0f * vx0 * gy0;
        float w10 = fx  * gy0f * vx1 * gy0;
        float w01 = gx0 * fy   * vx0 * gy1;
        float w11 = fx  * fy   * vx1 * gy1;
        wb00 = cvtf16x2(w00, w00);
        wb10 = cvtf16x2(w10, w10);
        wb01 = cvtf16x2(w01, w01);
        wb11 = cvtf16x2(w11, w11);
        int xc0 = min(max(x0, 0), 63), xc1 = min(max(x1, 0), 63);
        int yc0 = min(max(y0, 0), 63), yc1 = min(max(y1, 0), 63);
        o00 = (yc0 * 64 + xc0) * 128;
        o10 = (yc0 * 64 + xc1) * 128;
        o01 = (yc1 * 64 + xc0) * 128;
        o11 = (yc1 * 64 + xc1) * 128;
    }

    const u16* vbc = val + (((size_t)b << 12) * 128) + (hl << 3);
    float acc[8];
#pragma unroll
    for (int i = 0; i < 8; i++) acc[i] = 0.f;
    const unsigned FULL = 0xffffffffu;
    const int sbase = lane & 16;

#pragma unroll
    for (int k = 0; k < 9; ++k) {
        const int src = sbase | k;
        int a0 = __shfl_sync(FULL, o00, src);
        int a1 = __shfl_sync(FULL, o10, src);
        int a2 = __shfl_sync(FULL, o01, src);
        int a3 = __shfl_sync(FULL, o11, src);
        uint32_t u0 = __shfl_sync(FULL, wb00, src);
        uint32_t u1 = __shfl_sync(FULL, wb10, src);
        uint32_t u2 = __shfl_sync(FULL, wb01, src);
        uint32_t u3 = __shfl_sync(FULL, wb11, src);
        uint4 r0 = *(const uint4*)(vbc + a0);
        uint4 r1 = *(const uint4*)(vbc + a1);
        uint4 r2 = *(const uint4*)(vbc + a2);
        uint4 r3 = *(const uint4*)(vbc + a3);
        __half2 h0 = *(__half2*)&u0, h1 = *(__half2*)&u1;
        __half2 h2 = *(__half2*)&u2, h3 = *(__half2*)&u3;
        __half2 pa = __hmul2(h0, *(__half2*)&r0.x);
        __half2 pb = __hmul2(h0, *(__half2*)&r0.y);
        __half2 pc = __hmul2(h0, *(__half2*)&r0.z);
        __half2 pd = __hmul2(h0, *(__half2*)&r0.w);
        pa = __hfma2(h1, *(__half2*)&r1.x, pa);
        pb = __hfma2(h1, *(__half2*)&r1.y, pb);
        pc = __hfma2(h1, *(__half2*)&r1.z, pc);
        pd = __hfma2(h1, *(__half2*)&r1.w, pd);
        pa = __hfma2(h2, *(__half2*)&r2.x, pa);
        pb = __hfma2(h2, *(__half2*)&r2.y, pb);
        pc = __hfma2(h2, *(__half2*)&r2.z, pc);
        pd = __hfma2(h2, *(__half2*)&r2.w, pd);
        pa = __hfma2(h3, *(__half2*)&r3.x, pa);
        pb = __hfma2(h3, *(__half2*)&r3.y, pb);
        pc = __hfma2(h3, *(__half2*)&r3.z, pc);
        pd = __hfma2(h3, *(__half2*)&r3.w, pd);
        float2 fa = __half22float2(pa);
        float2 fb = __half22float2(pb);
        float2 fc = __half22float2(pc);
        float2 fd = __half22float2(pd);
        acc[0] += fa.x; acc[1] += fa.y; acc[2] += fb.x; acc[3] += fb.y;
        acc[4] += fc.x; acc[5] += fc.y; acc[6] += fd.x; acc[7] += fd.y;
    }
    uint4 o;
    o.x = cvtf16x2(acc[0], acc[1]);
    o.y = cvtf16x2(acc[2], acc[3]);
    o.z = cvtf16x2(acc[4], acc[5]);
    o.w = cvtf16x2(acc[6], acc[7]);
    *(uint4*)(oh + (size_t)pos * 128 + (hl << 3)) = o;
}

// ---------------------------------------------------------------------------
// Launcher
// ---------------------------------------------------------------------------
extern "C" void kernel_launch(void* const* d_in, const int* in_sizes, int n_in,
                              void* d_out, int out_size)
{
    (void)in_sizes; (void)n_in; (void)out_size;
    const float* x     = (const float*)d_in[0];
    const float* bn1_g = (const float*)d_in[1];
    const float* bn1_b = (const float*)d_in[2];
    const float* bn1_m = (const float*)d_in[3];
    const float* bn1_v = (const float*)d_in[4];
    const float* w_pw0 = (const float*)d_in[5];
    const float* w_vp  = (const float*)d_in[6];
    const float* b_vp  = (const float*)d_in[7];
    const float* w_om  = (const float*)d_in[8];
    const float* b_om  = (const float*)d_in[9];
    const float* w_op  = (const float*)d_in[10];
    const float* bn2_g = (const float*)d_in[11];
    const float* bn2_b = (const float*)d_in[12];
    const float* bn2_m = (const float*)d_in[13];
    const float* bn2_v = (const float*)d_in[14];
    const float* w_pw1 = (const float*)d_in[15];
    float* out = (float*)d_out;

    u16 *a2, *val, *dcn;
    u16 *w1h, *w1l, *w2h, *w2l, *w4h, *w5h, *w5l;
    float *omb, *op, *bias0, *bias1, *bcat, *zero;
    cudaGetSymbolAddress((void**)&a2, g_a2);
    cudaGetSymbolAddress((void**)&val, g_val);    cudaGetSymbolAddress((void**)&omb, g_om);
    cudaGetSymbolAddress((void**)&dcn, g_dcn);    cudaGetSymbolAddress((void**)&op, g_op);
    cudaGetSymbolAddress((void**)&w1h, g_w1h);    cudaGetSymbolAddress((void**)&w1l, g_w1l);
    cudaGetSymbolAddress((void**)&w2h, g_w2h);    cudaGetSymbolAddress((void**)&w2l, g_w2l);
    cudaGetSymbolAddress((void**)&w4h, g_w4h);
    cudaGetSymbolAddress((void**)&w5h, g_w5h);    cudaGetSymbolAddress((void**)&w5l, g_w5l);
    cudaGetSymbolAddress((void**)&bias0, g_bias0); cudaGetSymbolAddress((void**)&bias1, g_bias1);
    cudaGetSymbolAddress((void**)&bcat, g_bcat);  cudaGetSymbolAddress((void**)&zero, g_zero);

    // smem: Bh(N*256) + Bl(BLO*256) + A dbuf + stage (MODE1/2 only)
    const int SM_G1 = (128 + 128) * 256 + 2 * 128 * 272 + 64 * 129 * 4;  // 168192
    const int SM_G2 = (192 + 64) * 256 + 2 * 64 * 256;                   // 98304
    const int SM_G4 = (128 + 0) * 256 + 2 * 64 * 256;                    // 65536 -> 2 CTA/SM
    const int SM_G5 = (128 + 128) * 256 + 2 * 128 * 272 + 64 * 129 * 4;  // 168192
    cudaFuncSetAttribute((const void*)gemm_mma<128, 1, true, 128, 1>,
                         cudaFuncAttributeMaxDynamicSharedMemorySize, SM_G1);
    cudaFuncSetAttribute((const void*)gemm_mma<192, 3, false, 64, 1>,
                         cudaFuncAttributeMaxDynamicSharedMemorySize, SM_G2);
    cudaFuncSetAttribute((const void*)gemm_mma<128, 0, false, 0, 2>,
                         cudaFuncAttributeMaxDynamicSharedMemorySize, SM_G4);
    cudaFuncSetAttribute((const void*)gemm_mma<128, 2, true, 128, 1>,
                         cudaFuncAttributeMaxDynamicSharedMemorySize, SM_G5);

    prep_all<<<290, 256>>>(w_pw0, w_pw1, w_vp, w_om, w_op,
                           bn1_g, bn1_b, bn1_m, bn1_v,
                           bn2_g, bn2_b, bn2_m, bn2_v, b_vp, b_om);

    // 1) x1 = x(NCHW fp32 k-major) @ w1^T + bias0 -> fp16 single scatter (2-pass B)
    gemm_mma<128, 1, true, 128, 1><<<148, 256, SM_G1>>>(
        x, nullptr, w1h, w1l, bias0, nullptr, 0, a2);

    // 2) vpom split: value cols single-pass, om cols (128+) 2-pass;
    //    value -> fp16 g_val, offset/mask -> fp32 g_om (ld 64)
    gemm_mma<192, 3, false, 64, 1><<<148, 256, SM_G2>>>(
        nullptr, a2, w2h, w2l + 128 * 128, bcat, omb, 0, val);

    // 3) DCNv4 core (2 positions/warp, uint4 fp16 gathers) -> fp16 plane
    dcn_kernel<<<2048, 256>>>(val, omb, dcn);

    // 4) op = dcn @ w_op (single-pass B, 2 CTAs/SM) -> fp32 token-major
    gemm_mma<128, 0, false, 0, 2><<<296, 256, SM_G4>>>(
        nullptr, dcn, w4h, nullptr, zero, op, 128, nullptr);

    // 5) out = (BN2-folded pw1) @ op(NCHW view, fp32 k-major read) -> fp32 NCHW (2-pass B)
    gemm_mma<128, 2, true, 128, 1><<<148, 256, SM_G5>>>(
        op, nullptr, w5h, w5l, bias1, out, 0, nullptr);
}